// round 9
// baseline (speedup 1.0000x reference)
#include <cuda_runtime.h>
#include <cstdint>

#define HID   1024
#define BATCH 64
#define SEQ   512
#define G3    3072
#define BT    (BATCH * SEQ)
#define DIN0  118

#define NBLK  128          // persistent blocks (all co-resident; <= 148 SMs)
#define GNT   512          // 16 warps: wgk = warp>>2 (0..3) k-split, mt = warp&3
#define GKC   64           // k rows per staged h chunk (each wgk computes 16)
#define GHROW 68           // floats per smem h k-row (64 + 4 pad)
#define GW2   (HID * 24)   // float2 for weight hi/lo slice
// smem bytes: W2 (192 KB) + 2 h buffers (2*64*68*4 = 34816) = 231424
#define GSM_BYTES (GW2 * 8 + 2 * GKC * GHROW * 4)

// ---------------- scratch (device globals; no allocation allowed) ----------
__device__ float  g_xg[(size_t)BT * G3];      // input projections for current layer
__device__ float  g_yA[(size_t)BT * HID];     // layer outputs ping
__device__ float  g_yB[(size_t)BT * HID];     // layer outputs pong
__device__ float  g_hT[2][HID * BATCH];       // hidden fp32, [k][b], ping-pong
__device__ float  g_hb[BATCH * HID];          // final hidden, batch-major
__device__ unsigned long long g_flags[NBLK * 16];  // barrier flags, 128B stride
__device__ unsigned long long g_bar_epoch;         // barrier epoch broadcast

// ---------------------------------------------------------------------------
// flag-tree grid barrier: per-block flag stores (parallel) -> block 0 gathers
// -> epoch broadcast. Epochs absolute/monotonic across launches (64-bit).
// ---------------------------------------------------------------------------
__device__ __forceinline__ void grid_barrier(unsigned long long ep) {
    const int tid = threadIdx.x;
    const int bid = blockIdx.x;
    __threadfence();
    __syncthreads();                       // all block threads' writes fenced
    if (tid == 0)
        *(volatile unsigned long long*)&g_flags[bid * 16] = ep;
    if (bid == 0) {
        if (tid < NBLK) {
            while (*(volatile unsigned long long*)&g_flags[tid * 16] < ep)
                __nanosleep(32);
        }
        __syncthreads();                   // block 0: all flags seen
        if (tid == 0) {
            __threadfence();
            *(volatile unsigned long long*)&g_bar_epoch = ep;
        }
    }
    if (tid == 0) {
        while (*(volatile unsigned long long*)&g_bar_epoch < ep)
            __nanosleep(32);
    }
    __syncthreads();
    __threadfence();
}

__device__ __forceinline__ float fsigmoid(float x) {
    return 1.f / (1.f + __expf(-x));
}
__device__ __forceinline__ float ftanh(float x) {
    return 2.f / (1.f + __expf(-2.f * x)) - 1.f;
}

// ---------------------------------------------------------------------------
// cp.async / tf32 helpers
// ---------------------------------------------------------------------------
__device__ __forceinline__ void cp_async16(uint32_t smem_dst, const void* gptr) {
    asm volatile("cp.async.cg.shared.global [%0], [%1], 16;\n"
                 :: "r"(smem_dst), "l"(gptr));
}
__device__ __forceinline__ void cp_commit() {
    asm volatile("cp.async.commit_group;\n");
}
__device__ __forceinline__ void cp_wait1() {
    asm volatile("cp.async.wait_group 1;\n");
}
__device__ __forceinline__ void cp_wait0() {
    asm volatile("cp.async.wait_group 0;\n");
}
__device__ __forceinline__ uint32_t f2tf32(float x) {
    uint32_t r;
    asm("cvt.rna.tf32.f32 %0, %1;" : "=r"(r) : "f"(x));
    return r;
}
__device__ __forceinline__ void mma_tf32(
    float& c0, float& c1, float& c2, float& c3,
    uint32_t a0, uint32_t a1, uint32_t a2, uint32_t a3,
    uint32_t b0, uint32_t b1)
{
    asm volatile(
        "mma.sync.aligned.m16n8k8.row.col.f32.tf32.tf32.f32 "
        "{%0,%1,%2,%3}, {%4,%5,%6,%7}, {%8,%9}, {%0,%1,%2,%3};"
        : "+f"(c0), "+f"(c1), "+f"(c2), "+f"(c3)
        : "r"(a0), "r"(a1), "r"(a2), "r"(a3), "r"(b0), "r"(b1));
}

// ---------------------------------------------------------------------------
// Persistent per-layer GRU kernel — tf32x3 mma recurrence, 16 warps (4/SMSP).
// Block i owns HID cols c0..c0+7 (c0=8i) for all 3 gates.
//   smem: W2[k][j] float2(hi,lo), j = gate*8+col   (192 KB resident)
//         h: 2 x [GKC=64 k-rows][68 floats] fp32 staging (34 KB, cp.async DB)
// Warp w: m-tile (w&3) [batches 16(w&3)..+15], k-quarter (w>>2) of each chunk
// (16 k-rows = 2 ks slices). Per step: GEMM (16 chunks) -> wgk 1..3 partials
// to smem -> wg0 adds -> gates in register (wg0) -> ONE flag-tree barrier.
// ---------------------------------------------------------------------------
__global__ __launch_bounds__(GNT, 1) void gru_layer_kernel(
    const float* __restrict__ Whh, const float* __restrict__ bhh, int ysel)
{
    extern __shared__ float2 sm2[];
    float2* W2  = sm2;                         // GW2 float2
    float*  HBf = (float*)(sm2 + GW2);         // 2 * GKC * GHROW floats

    const int tid  = threadIdx.x;
    const int bid  = blockIdx.x;
    const int c0   = bid * 8;
    const int warp = tid >> 5;
    const int lane = tid & 31;
    const int mt   = warp & 3;                 // m-tile
    const int wgk  = warp >> 2;                // k-quarter within chunk (0..3)
    const int l4   = lane >> 2;                // 0..7
    const int tq   = lane & 3;                 // 0..3

    // ---- pre-split Whh slice into smem hi/lo (once) ----
    for (int idx = tid; idx < 24 * HID; idx += GNT) {
        int j = idx >> 10;                     // 0..23 = gate*8 + col
        int k = idx & (HID - 1);
        int jg = j >> 3, jc = j & 7;
        float w  = Whh[(size_t)(jg * HID + c0 + jc) * HID + k];
        float wh = __uint_as_float(f2tf32(w));
        W2[k * 24 + j] = make_float2(wh, __uint_as_float(f2tf32(w - wh)));
    }

    // gate constants (used by wg0 only)
    const int cA = c0 + 2 * tq;
    const int bA = mt * 16 + l4;
    float bh[3][2];
#pragma unroll
    for (int gte = 0; gte < 3; gte++) {
        bh[gte][0] = bhh[gte * HID + cA];
        bh[gte][1] = bhh[gte * HID + cA + 1];
    }

    float hp[4] = {0.f, 0.f, 0.f, 0.f};        // h_prev cells (wg0)

    unsigned long long ep = *(volatile unsigned long long*)&g_bar_epoch;
    const uint32_t s_hb = (uint32_t)__cvta_generic_to_shared(HBf);

    for (int t = 0; t < SEQ; t++) {
        // ---- prefetch xg for this step's gate cells (wg0 only) ----
        float xv[3][4];
        if (wgk == 0) {
            const size_t rA = ((size_t)bA * SEQ + t) * G3;
            const size_t rB = ((size_t)(bA + 8) * SEQ + t) * G3;
#pragma unroll
            for (int gte = 0; gte < 3; gte++) {
                xv[gte][0] = __ldcg(&g_xg[rA + gte * HID + cA]);
                xv[gte][1] = __ldcg(&g_xg[rA + gte * HID + cA + 1]);
                xv[gte][2] = __ldcg(&g_xg[rB + gte * HID + cA]);
                xv[gte][3] = __ldcg(&g_xg[rB + gte * HID + cA + 1]);
            }
        }

        float acc[3][4];
#pragma unroll
        for (int nt = 0; nt < 3; nt++)
#pragma unroll
            for (int r = 0; r < 4; r++) acc[nt][r] = 0.f;

        if (t > 0) {
            const float* hsrc = g_hT[t & 1];

            // stage chunks 0,1: 64 k-rows x 64 floats, rows padded to 68
#pragma unroll
            for (int ch = 0; ch < 2; ch++) {
                uint32_t dst = s_hb + (uint32_t)(ch & 1) * (GKC * GHROW * 4);
                const float* src = hsrc + (size_t)ch * GKC * BATCH;
#pragma unroll
                for (int j = 0; j < (GKC * 16) / GNT; j++) {   // 2 ops/thread
                    int o = tid + j * GNT;
                    int k = o >> 4, s = o & 15;                // s = 16B seg
                    cp_async16(dst + (uint32_t)(k * GHROW + s * 4) * 4,
                               src + (size_t)k * BATCH + s * 4);
                }
                cp_commit();
            }

#pragma unroll 1
            for (int ch = 0; ch < HID / GKC; ch++) {           // 16 chunks
                cp_wait1();
                __syncthreads();
                const float* hb = HBf + (ch & 1) * (GKC * GHROW) + wgk * 16 * GHROW;
                const int kg = ch * GKC + wgk * 16;

#pragma unroll
                for (int ks = 0; ks < 2; ks++) {
                    const int kk = ks * 8;
                    // A fragments (h fp32 -> hi/lo on the fly)
                    float a0 = hb[(kk + tq) * GHROW + bA];
                    float a1 = hb[(kk + tq) * GHROW + bA + 8];
                    float a2 = hb[(kk + tq + 4) * GHROW + bA];
                    float a3 = hb[(kk + tq + 4) * GHROW + bA + 8];
                    uint32_t ah0 = f2tf32(a0), al0 = f2tf32(a0 - __uint_as_float(ah0));
                    uint32_t ah1 = f2tf32(a1), al1 = f2tf32(a1 - __uint_as_float(ah1));
                    uint32_t ah2 = f2tf32(a2), al2 = f2tf32(a2 - __uint_as_float(ah2));
                    uint32_t ah3 = f2tf32(a3), al3 = f2tf32(a3 - __uint_as_float(ah3));
#pragma unroll
                    for (int nt = 0; nt < 3; nt++) {
                        int j = nt * 8 + l4;
                        float2 b0 = W2[(kg + kk + tq) * 24 + j];
                        float2 b1 = W2[(kg + kk + tq + 4) * 24 + j];
                        uint32_t bh0 = __float_as_uint(b0.x), bl0 = __float_as_uint(b0.y);
                        uint32_t bh1 = __float_as_uint(b1.x), bl1 = __float_as_uint(b1.y);
                        float* c = acc[nt];
                        mma_tf32(c[0], c[1], c[2], c[3], ah0, ah1, ah2, ah3, bh0, bh1);
                        mma_tf32(c[0], c[1], c[2], c[3], ah0, ah1, ah2, ah3, bl0, bl1);
                        mma_tf32(c[0], c[1], c[2], c[3], al0, al1, al2, al3, bh0, bh1);
                    }
                }
                __syncthreads();
                if (ch + 2 < HID / GKC) {
                    uint32_t dst = s_hb + (uint32_t)(ch & 1) * (GKC * GHROW * 4);
                    const float* src = hsrc + (size_t)(ch + 2) * GKC * BATCH;
#pragma unroll
                    for (int j = 0; j < (GKC * 16) / GNT; j++) {
                        int o = tid + j * GNT;
                        int k = o >> 4, s = o & 15;
                        cp_async16(dst + (uint32_t)(k * GHROW + s * 4) * 4,
                                   src + (size_t)k * BATCH + s * 4);
                    }
                }
                cp_commit();
            }

            // ---- cross-warpgroup acc reduction (reuse h staging as scratch) --
            // wgk 1..3 write partials; wg0 adds. 3 * 128 threads * 12 floats.
            cp_wait0();
            __syncthreads();
            float* red = HBf;
            if (wgk != 0) {
                int o = ((wgk - 1) * 128 + mt * 32 + lane) * 12;
#pragma unroll
                for (int nt = 0; nt < 3; nt++)
#pragma unroll
                    for (int r = 0; r < 4; r++)
                        red[o + nt * 4 + r] = acc[nt][r];
            }
            __syncthreads();
            if (wgk == 0) {
#pragma unroll
                for (int s = 0; s < 3; s++) {
                    int o = (s * 128 + mt * 32 + lane) * 12;
#pragma unroll
                    for (int nt = 0; nt < 3; nt++)
#pragma unroll
                        for (int r = 0; r < 4; r++)
                            acc[nt][r] += red[o + nt * 4 + r];
                }
            }
        }

        // ---- gates, in register (wg0 only) ----
        if (wgk == 0) {
            float* hdst = g_hT[(t + 1) & 1];
#pragma unroll
            for (int r = 0; r < 4; r++) {
                int i  = r >> 1, jj = r & 1;
                int b  = bA + 8 * i;
                int cc = cA + jj;
                int ar = 2 * i + jj;
                float rg = fsigmoid(xv[0][2 * i + jj] + acc[0][ar] + bh[0][jj]);
                float zg = fsigmoid(xv[1][2 * i + jj] + acc[1][ar] + bh[1][jj]);
                float ng = ftanh(xv[2][2 * i + jj] + rg * (acc[2][ar] + bh[2][jj]));
                float h  = (1.f - zg) * ng + zg * hp[r];
                hp[r] = h;

                hdst[(size_t)cc * BATCH + b] = h;

                size_t bt = (size_t)b * SEQ + t;
                if (ysel == 1)      g_yA[bt * HID + cc] = h;
                else if (ysel == 2) g_yB[bt * HID + cc] = h;
                if (t == SEQ - 1)   g_hb[(size_t)b * HID + cc] = h;
            }
        }

        grid_barrier(++ep);
    }
}

// ---------------------------------------------------------------------------
// tf32 split-3 MMA GEMM for xg of layers 1,2 (K = 1024). (unchanged, passing)
// ---------------------------------------------------------------------------
#define XKC   32
#define XLD   36
#define XA_F  (128 * XLD)
#define XB_F  (64 * XLD)
#define XST_F (XA_F + XB_F)

__global__ __launch_bounds__(128, 2) void gemm_xg_tf32_kernel(
    int a_sel, const float* __restrict__ W, const float* __restrict__ bias)
{
    const float* A = (a_sel == 1) ? g_yA : g_yB;
    const int K = HID;

    extern __shared__ float xs[];
    const int tid  = threadIdx.x;
    const int warp = tid >> 5;
    const int lane = tid & 31;
    const int g    = lane >> 2;
    const int tq   = lane & 3;

    const int n0 = blockIdx.x * 64;
    const int m0 = blockIdx.y * 128;
    const int wm = (warp & 1) * 64;
    const int wn = (warp >> 1) * 32;

    const uint32_t s_base = (uint32_t)__cvta_generic_to_shared(xs);

    float acc[4][4][4];
#pragma unroll
    for (int mi = 0; mi < 4; mi++)
#pragma unroll
        for (int ni = 0; ni < 4; ni++)
#pragma unroll
            for (int r = 0; r < 4; r++) acc[mi][ni][r] = 0.f;

    auto load_stage = [&](int ch, int buf) {
        const int k0 = ch * XKC;
        uint32_t dstA = s_base + (uint32_t)buf * XST_F * 4;
        uint32_t dstB = dstA + XA_F * 4;
#pragma unroll
        for (int j = 0; j < 8; j++) {
            int o = tid + j * 128;
            int row = o >> 3, seg = o & 7;
            cp_async16(dstA + (uint32_t)(row * XLD + seg * 4) * 4,
                       A + (size_t)(m0 + row) * K + k0 + seg * 4);
        }
#pragma unroll
        for (int j = 0; j < 4; j++) {
            int o = tid + j * 128;
            int row = o >> 3, seg = o & 7;
            cp_async16(dstB + (uint32_t)(row * XLD + seg * 4) * 4,
                       W + (size_t)(n0 + row) * K + k0 + seg * 4);
        }
    };

    const int NCH = K / XKC;
    load_stage(0, 0); cp_commit();
    load_stage(1, 1); cp_commit();

    for (int ch = 0; ch < NCH; ch++) {
        cp_wait1();
        __syncthreads();
        const float* As = xs + (ch & 1) * XST_F;
        const float* Bs = As + XA_F;

#pragma unroll
        for (int ks = 0; ks < 4; ks++) {
            const int k = ks * 8;
            uint32_t ahi[4][4], alo[4][4];
#pragma unroll
            for (int mi = 0; mi < 4; mi++) {
                int rbase = wm + mi * 16 + g;
                float r0 = As[(rbase)     * XLD + k + tq];
                float r1 = As[(rbase + 8) * XLD + k + tq];
                float r2 = As[(rbase)     * XLD + k + tq + 4];
                float r3 = As[(rbase + 8) * XLD + k + tq + 4];
                ahi[mi][0] = f2tf32(r0); alo[mi][0] = f2tf32(r0 - __uint_as_float(ahi[mi][0]));
                ahi[mi][1] = f2tf32(r1); alo[mi][1] = f2tf32(r1 - __uint_as_float(ahi[mi][1]));
                ahi[mi][2] = f2tf32(r2); alo[mi][2] = f2tf32(r2 - __uint_as_float(ahi[mi][2]));
                ahi[mi][3] = f2tf32(r3); alo[mi][3] = f2tf32(r3 - __uint_as_float(ahi[mi][3]));
            }
            uint32_t bhi[4][2], blo[4][2];
#pragma unroll
            for (int ni = 0; ni < 4; ni++) {
                int nbase = wn + ni * 8 + g;
                float r0 = Bs[nbase * XLD + k + tq];
                float r1 = Bs[nbase * XLD + k + tq + 4];
                bhi[ni][0] = f2tf32(r0); blo[ni][0] = f2tf32(r0 - __uint_as_float(bhi[ni][0]));
                bhi[ni][1] = f2tf32(r1); blo[ni][1] = f2tf32(r1 - __uint_as_float(bhi[ni][1]));
            }
#pragma unroll
            for (int mi = 0; mi < 4; mi++)
#pragma unroll
                for (int ni = 0; ni < 4; ni++) {
                    float* c = acc[mi][ni];
                    mma_tf32(c[0], c[1], c[2], c[3],
                             ahi[mi][0], ahi[mi][1], ahi[mi][2], ahi[mi][3],
                             bhi[ni][0], bhi[ni][1]);
                    mma_tf32(c[0], c[1], c[2], c[3],
                             ahi[mi][0], ahi[mi][1], ahi[mi][2], ahi[mi][3],
                             blo[ni][0], blo[ni][1]);
                    mma_tf32(c[0], c[1], c[2], c[3],
                             alo[mi][0], alo[mi][1], alo[mi][2], alo[mi][3],
                             bhi[ni][0], bhi[ni][1]);
                }
        }

        __syncthreads();
        if (ch + 2 < NCH) load_stage(ch + 2, ch & 1);
        cp_commit();
    }

#pragma unroll
    for (int mi = 0; mi < 4; mi++) {
        int r0 = m0 + wm + mi * 16 + g;
#pragma unroll
        for (int ni = 0; ni < 4; ni++) {
            int cb = n0 + wn + ni * 8 + 2 * tq;
            float2 bia = *(const float2*)&bias[cb];
            float* c = acc[mi][ni];
            *(float2*)&g_xg[(size_t)r0 * G3 + cb] =
                make_float2(c[0] + bia.x, c[1] + bia.y);
            *(float2*)&g_xg[(size_t)(r0 + 8) * G3 + cb] =
                make_float2(c[2] + bia.x, c[3] + bia.y);
        }
    }
}

// ---------------------------------------------------------------------------
// fp32 SGEMM for layer-0 xg (K = 118). (unchanged, passing)
// ---------------------------------------------------------------------------
__global__ __launch_bounds__(256) void gemm_xg_kernel(
    const float* __restrict__ x_in, int K,
    const float* __restrict__ W, const float* __restrict__ bias)
{
    const float* A = x_in;

    __shared__ float As[8][128];
    __shared__ float Bs[8][128];

    const int n0 = blockIdx.x * 128;
    const int m0 = blockIdx.y * 128;
    const int tid = threadIdx.x;
    const int tx = tid & 15;
    const int ty = tid >> 4;

    float acc[8][8];
#pragma unroll
    for (int i = 0; i < 8; i++)
#pragma unroll
        for (int j = 0; j < 8; j++) acc[i][j] = 0.f;

    const int nkt = (K + 7) >> 3;
    for (int kt = 0; kt < nkt; kt++) {
        const int k0 = kt << 3;
#pragma unroll
        for (int i = 0; i < 4; i++) {
            int ii = tid + i * 256;
            int m = ii >> 3, k = ii & 7;
            As[k][m] = (k0 + k < K) ? A[(size_t)(m0 + m) * K + (k0 + k)] : 0.f;
        }
#pragma unroll
        for (int i = 0; i < 4; i++) {
            int ii = tid + i * 256;
            int n = ii >> 3, k = ii & 7;
            Bs[k][n] = (k0 + k < K) ? W[(size_t)(n0 + n) * K + (k0 + k)] : 0.f;
        }
        __syncthreads();
#pragma unroll
        for (int k = 0; k < 8; k++) {
            float a[8], b[8];
#pragma unroll
            for (int i = 0; i < 8; i++) a[i] = As[k][ty * 8 + i];
#pragma unroll
            for (int j = 0; j < 8; j++) b[j] = Bs[k][tx * 8 + j];
#pragma unroll
            for (int i = 0; i < 8; i++)
#pragma unroll
                for (int j = 0; j < 8; j++)
                    acc[i][j] = fmaf(a[i], b[j], acc[i][j]);
        }
        __syncthreads();
    }

#pragma unroll
    for (int i = 0; i < 8; i++) {
        size_t row = (size_t)(m0 + ty * 8 + i) * G3;
#pragma unroll
        for (int j = 0; j < 8; j++) {
            int n = n0 + tx * 8 + j;
            g_xg[row + n] = acc[i][j] + bias[n];
        }
    }
}

// ---------------------------------------------------------------------------
// Final linear: out[b] = dot(h_last[b,:], W_lin) + b_lin
// ---------------------------------------------------------------------------
__global__ __launch_bounds__(256) void final_kernel(
    const float* __restrict__ Wlin, const float* __restrict__ blin,
    float* __restrict__ out)
{
    const int b = blockIdx.x;
    const float* h = g_hb + b * HID;
    float s = 0.f;
    for (int k = threadIdx.x; k < HID; k += 256) s += h[k] * Wlin[k];
#pragma unroll
    for (int o = 16; o > 0; o >>= 1) s += __shfl_down_sync(0xffffffffu, s, o);
    __shared__ float red[8];
    if ((threadIdx.x & 31) == 0) red[threadIdx.x >> 5] = s;
    __syncthreads();
    if (threadIdx.x < 8) {
        s = red[threadIdx.x];
#pragma unroll
        for (int o = 4; o > 0; o >>= 1) s += __shfl_down_sync(0xffu, s, o);
        if (threadIdx.x == 0) out[b] = s + blin[0];
    }
}

// ---------------------------------------------------------------------------
extern "C" void kernel_launch(void* const* d_in, const int* in_sizes, int n_in,
                              void* d_out, int out_size)
{
    const float* x      = (const float*)d_in[0];
    const float* W_ih0  = (const float*)d_in[1];
    const float* W_ih12 = (const float*)d_in[2];
    const float* W_hh   = (const float*)d_in[3];
    const float* b_ih   = (const float*)d_in[4];
    const float* b_hh   = (const float*)d_in[5];
    const float* W_lin  = (const float*)d_in[6];
    const float* b_lin  = (const float*)d_in[7];
    float* out = (float*)d_out;

    cudaFuncSetAttribute(gru_layer_kernel,
                         cudaFuncAttributeMaxDynamicSharedMemorySize, GSM_BYTES);
    const int smem_xg = 2 * XST_F * sizeof(float);
    cudaFuncSetAttribute(gemm_xg_tf32_kernel,
                         cudaFuncAttributeMaxDynamicSharedMemorySize, smem_xg);

    for (int l = 0; l < 3; l++) {
        const int    ysel  = (l == 0) ? 1 : (l == 1 ? 2 : 0);
        const float* Whh_l = W_hh + (size_t)l * G3 * HID;
        const float* bih_l = b_ih + (size_t)l * G3;
        const float* bhh_l = b_hh + (size_t)l * G3;

        if (l == 0) {
            dim3 ggrid(G3 / 128, BT / 128);
            gemm_xg_kernel<<<ggrid, 256>>>(x, DIN0, W_ih0, bih_l);
        } else {
            const float* Wih = W_ih12 + (size_t)(l - 1) * G3 * HID;
            dim3 ggrid(G3 / 64, BT / 128);
            gemm_xg_tf32_kernel<<<ggrid, 128, smem_xg>>>(l, Wih, bih_l);
        }

        gru_layer_kernel<<<NBLK, GNT, GSM_BYTES>>>(Whh_l, bhh_l, ysel);
    }

    final_kernel<<<BATCH, 256>>>(W_lin, b_lin, out);
}

// round 10
// speedup vs baseline: 1.1381x; 1.1381x over previous
#include <cuda_runtime.h>
#include <cuda_bf16.h>
#include <cstdint>

#define HID   1024
#define BATCH 64
#define SEQ   512
#define G3    3072
#define BT    (BATCH * SEQ)
#define DIN0  118

#define NBLK  128          // persistent blocks (all co-resident; <= 148 SMs)
#define GNT   256          // 8 warps: mt = warp&3 (m-tile), wgk = warp>>2 (k-half)
#define GKC   64           // k rows per staged h chunk (each wgk computes 32)
#define GHROW 68           // floats per smem h k-row (64 + 4 pad)
#define NSTG  4            // h ring stages
// smem: W_hi u32[1024][24] (96KB) + h ring 4*64*68*4 (69632) + W_lo u16[1024][24] (48KB)
#define WHI_WORDS (HID * 24)
#define HBUF_FLOATS (GKC * GHROW)
#define SM_WHI_OFF 0
#define SM_HB_OFF  (WHI_WORDS * 4)                         // 98304
#define SM_WLO_OFF (SM_HB_OFF + NSTG * HBUF_FLOATS * 4)    // 167936
#define GSM_BYTES  (SM_WLO_OFF + HID * 24 * 2)             // 217088

// ---------------- scratch (device globals; no allocation allowed) ----------
__device__ float  g_xg[(size_t)BT * G3];      // input projections for current layer
__device__ float  g_yA[(size_t)BT * HID];     // layer outputs ping
__device__ float  g_yB[(size_t)BT * HID];     // layer outputs pong
__device__ float  g_hT[2][HID * BATCH];       // hidden fp32, [k][b], ping-pong
__device__ float  g_hb[BATCH * HID];          // final hidden, batch-major
__device__ unsigned long long g_flags[NBLK * 16];  // barrier flags, 128B stride
__device__ unsigned long long g_bar_epoch;         // barrier epoch broadcast

// ---------------------------------------------------------------------------
// flag-tree grid barrier (proven in R8/R9). Epochs absolute/monotonic.
// ---------------------------------------------------------------------------
__device__ __forceinline__ void grid_barrier(unsigned long long ep) {
    const int tid = threadIdx.x;
    const int bid = blockIdx.x;
    __threadfence();
    __syncthreads();
    if (tid == 0)
        *(volatile unsigned long long*)&g_flags[bid * 16] = ep;
    if (bid == 0) {
        if (tid < NBLK) {
            while (*(volatile unsigned long long*)&g_flags[tid * 16] < ep)
                __nanosleep(32);
        }
        __syncthreads();
        if (tid == 0) {
            __threadfence();
            *(volatile unsigned long long*)&g_bar_epoch = ep;
        }
    }
    if (tid == 0) {
        while (*(volatile unsigned long long*)&g_bar_epoch < ep)
            __nanosleep(32);
    }
    __syncthreads();
    __threadfence();
}

__device__ __forceinline__ float fsigmoid(float x) {
    return 1.f / (1.f + __expf(-x));
}
__device__ __forceinline__ float ftanh(float x) {
    return 2.f / (1.f + __expf(-2.f * x)) - 1.f;
}

// ---------------------------------------------------------------------------
// cp.async / tf32 helpers
// ---------------------------------------------------------------------------
__device__ __forceinline__ void cp_async16(uint32_t smem_dst, const void* gptr) {
    asm volatile("cp.async.cg.shared.global [%0], [%1], 16;\n"
                 :: "r"(smem_dst), "l"(gptr));
}
__device__ __forceinline__ void cp_commit() {
    asm volatile("cp.async.commit_group;\n");
}
template <int N>
__device__ __forceinline__ void cp_wait() {
    asm volatile("cp.async.wait_group %0;\n" :: "n"(N));
}
__device__ __forceinline__ uint32_t f2tf32(float x) {
    uint32_t r;
    asm("cvt.rna.tf32.f32 %0, %1;" : "=r"(r) : "f"(x));
    return r;
}
__device__ __forceinline__ void mma_tf32(
    float& c0, float& c1, float& c2, float& c3,
    uint32_t a0, uint32_t a1, uint32_t a2, uint32_t a3,
    uint32_t b0, uint32_t b1)
{
    asm volatile(
        "mma.sync.aligned.m16n8k8.row.col.f32.tf32.tf32.f32 "
        "{%0,%1,%2,%3}, {%4,%5,%6,%7}, {%8,%9}, {%0,%1,%2,%3};"
        : "+f"(c0), "+f"(c1), "+f"(c2), "+f"(c3)
        : "r"(a0), "r"(a1), "r"(a2), "r"(a3), "r"(b0), "r"(b1));
}

// ---------------------------------------------------------------------------
// Persistent per-layer GRU kernel — tf32x3 mma recurrence (R8 topology) with
//  * W_lo stored as bf16 (smem 192->144 KB)
//  * 4-stage cp.async h ring, ONE __syncthreads per chunk, prefetch depth 3
//  * B fragments via conflict-free LDS.32
// Block i owns HID cols c0..c0+7 (c0=8i) for all 3 gates.
// Warp w: m-tile (w&3), k-half (w>>2) of each 64-row chunk.
// ---------------------------------------------------------------------------
__global__ __launch_bounds__(GNT, 1) void gru_layer_kernel(
    const float* __restrict__ Whh, const float* __restrict__ bhh, int ysel)
{
    extern __shared__ char smraw[];
    uint32_t* W_hi = (uint32_t*)(smraw + SM_WHI_OFF);   // [k*24 + j]
    float*    HBf  = (float*)(smraw + SM_HB_OFF);       // 4 x [64][68]
    uint16_t* W_lo = (uint16_t*)(smraw + SM_WLO_OFF);   // [k*24 + j] bf16 bits

    const int tid  = threadIdx.x;
    const int bid  = blockIdx.x;
    const int c0   = bid * 8;
    const int warp = tid >> 5;
    const int lane = tid & 31;
    const int mt   = warp & 3;                 // m-tile
    const int wgk  = warp >> 2;                // k-half within chunk (0/1)
    const int l4   = lane >> 2;                // 0..7
    const int tq   = lane & 3;                 // 0..3

    // ---- pre-split Whh slice: hi = tf32(w) (u32), lo = bf16(w - hi) ----
    for (int idx = tid; idx < 24 * HID; idx += GNT) {
        int j = idx >> 10;                     // 0..23 = gate*8 + col
        int k = idx & (HID - 1);
        int jg = j >> 3, jc = j & 7;
        float w  = Whh[(size_t)(jg * HID + c0 + jc) * HID + k];
        uint32_t wh = f2tf32(w);
        W_hi[k * 24 + j] = wh;
        __nv_bfloat16 wl = __float2bfloat16(w - __uint_as_float(wh));
        W_lo[k * 24 + j] = *(uint16_t*)&wl;
    }

    // gate constants (used by wg0 only)
    const int cA = c0 + 2 * tq;
    const int bA = mt * 16 + l4;
    float bh[3][2];
#pragma unroll
    for (int gte = 0; gte < 3; gte++) {
        bh[gte][0] = bhh[gte * HID + cA];
        bh[gte][1] = bhh[gte * HID + cA + 1];
    }

    float hp[4] = {0.f, 0.f, 0.f, 0.f};        // h_prev cells (wg0)

    unsigned long long ep = *(volatile unsigned long long*)&g_bar_epoch;
    const uint32_t s_hb = (uint32_t)__cvta_generic_to_shared(HBf);

    for (int t = 0; t < SEQ; t++) {
        // ---- prefetch xg for this step's gate cells (wg0 only) ----
        float xv[3][4];
        if (wgk == 0) {
            const size_t rA = ((size_t)bA * SEQ + t) * G3;
            const size_t rB = ((size_t)(bA + 8) * SEQ + t) * G3;
#pragma unroll
            for (int gte = 0; gte < 3; gte++) {
                xv[gte][0] = __ldcg(&g_xg[rA + gte * HID + cA]);
                xv[gte][1] = __ldcg(&g_xg[rA + gte * HID + cA + 1]);
                xv[gte][2] = __ldcg(&g_xg[rB + gte * HID + cA]);
                xv[gte][3] = __ldcg(&g_xg[rB + gte * HID + cA + 1]);
            }
        }

        float acc[3][4];
#pragma unroll
        for (int nt = 0; nt < 3; nt++)
#pragma unroll
            for (int r = 0; r < 4; r++) acc[nt][r] = 0.f;

        if (t > 0) {
            const float* hsrc = g_hT[t & 1];

            // prologue: stage chunks 0,1,2 into ring slots 0,1,2
#pragma unroll
            for (int ch = 0; ch < NSTG - 1; ch++) {
                uint32_t dst = s_hb + (uint32_t)ch * (HBUF_FLOATS * 4);
                const float* src = hsrc + (size_t)ch * GKC * BATCH;
#pragma unroll
                for (int j = 0; j < (GKC * 16) / GNT; j++) {   // 4 ops/thread
                    int o = tid + j * GNT;
                    int k = o >> 4, s = o & 15;
                    cp_async16(dst + (uint32_t)(k * GHROW + s * 4) * 4,
                               src + (size_t)k * BATCH + s * 4);
                }
                cp_commit();
            }

#pragma unroll 1
            for (int ch = 0; ch < HID / GKC; ch++) {           // 16 chunks
                cp_wait<NSTG - 2>();           // chunk ch resident
                __syncthreads();               // single sync per chunk
                const float* hb = HBf + (ch & 3) * HBUF_FLOATS + wgk * 32 * GHROW;
                const int kg = ch * GKC + wgk * 32;

#pragma unroll
                for (int ks = 0; ks < 4; ks++) {
                    const int kk = ks * 8;
                    // A fragments (h fp32 -> hi/lo on the fly)
                    float a0 = hb[(kk + tq) * GHROW + bA];
                    float a1 = hb[(kk + tq) * GHROW + bA + 8];
                    float a2 = hb[(kk + tq + 4) * GHROW + bA];
                    float a3 = hb[(kk + tq + 4) * GHROW + bA + 8];
                    uint32_t ah0 = f2tf32(a0), al0 = f2tf32(a0 - __uint_as_float(ah0));
                    uint32_t ah1 = f2tf32(a1), al1 = f2tf32(a1 - __uint_as_float(ah1));
                    uint32_t ah2 = f2tf32(a2), al2 = f2tf32(a2 - __uint_as_float(ah2));
                    uint32_t ah3 = f2tf32(a3), al3 = f2tf32(a3 - __uint_as_float(ah3));
#pragma unroll
                    for (int nt = 0; nt < 3; nt++) {
                        int j = nt * 8 + l4;
                        int w0 = (kg + kk + tq) * 24 + j;
                        int w1 = (kg + kk + tq + 4) * 24 + j;
                        uint32_t bh0 = W_hi[w0];
                        uint32_t bh1 = W_hi[w1];
                        uint32_t bl0 = ((uint32_t)W_lo[w0]) << 16;
                        uint32_t bl1 = ((uint32_t)W_lo[w1]) << 16;
                        float* c = acc[nt];
                        mma_tf32(c[0], c[1], c[2], c[3], ah0, ah1, ah2, ah3, bh0, bh1);
                        mma_tf32(c[0], c[1], c[2], c[3], ah0, ah1, ah2, ah3, bl0, bl1);
                        mma_tf32(c[0], c[1], c[2], c[3], al0, al1, al2, al3, bh0, bh1);
                    }
                }
                // stage chunk ch+3 into ring slot (ch+3)&3 (== slot of ch-1,
                // whose readers all passed this iteration's __syncthreads)
                if (ch + NSTG - 1 < HID / GKC) {
                    int cn = ch + NSTG - 1;
                    uint32_t dst = s_hb + (uint32_t)(cn & 3) * (HBUF_FLOATS * 4);
                    const float* src = hsrc + (size_t)cn * GKC * BATCH;
#pragma unroll
                    for (int j = 0; j < (GKC * 16) / GNT; j++) {
                        int o = tid + j * GNT;
                        int k = o >> 4, s = o & 15;
                        cp_async16(dst + (uint32_t)(k * GHROW + s * 4) * 4,
                                   src + (size_t)k * BATCH + s * 4);
                    }
                }
                cp_commit();                   // uniform (possibly empty) commit
            }

            // ---- cross-warpgroup acc reduction (reuse h ring as scratch) ----
            cp_wait<0>();
            __syncthreads();
            float* red = HBf;                  // 128 threads x 12 floats
            if (wgk == 1) {
                int o = (mt * 32 + lane) * 12;
#pragma unroll
                for (int nt = 0; nt < 3; nt++)
#pragma unroll
                    for (int r = 0; r < 4; r++)
                        red[o + nt * 4 + r] = acc[nt][r];
            }
            __syncthreads();
            if (wgk == 0) {
                int o = (mt * 32 + lane) * 12;
#pragma unroll
                for (int nt = 0; nt < 3; nt++)
#pragma unroll
                    for (int r = 0; r < 4; r++)
                        acc[nt][r] += red[o + nt * 4 + r];
            }
        }

        // ---- gates, in register (wg0 only) ----
        if (wgk == 0) {
            float* hdst = g_hT[(t + 1) & 1];
#pragma unroll
            for (int r = 0; r < 4; r++) {
                int i  = r >> 1, jj = r & 1;
                int b  = bA + 8 * i;
                int cc = cA + jj;
                int ar = 2 * i + jj;
                float rg = fsigmoid(xv[0][2 * i + jj] + acc[0][ar] + bh[0][jj]);
                float zg = fsigmoid(xv[1][2 * i + jj] + acc[1][ar] + bh[1][jj]);
                float ng = ftanh(xv[2][2 * i + jj] + rg * (acc[2][ar] + bh[2][jj]));
                float h  = (1.f - zg) * ng + zg * hp[r];
                hp[r] = h;

                hdst[(size_t)cc * BATCH + b] = h;

                size_t bt = (size_t)b * SEQ + t;
                if (ysel == 1)      g_yA[bt * HID + cc] = h;
                else if (ysel == 2) g_yB[bt * HID + cc] = h;
                if (t == SEQ - 1)   g_hb[(size_t)b * HID + cc] = h;
            }
        }

        grid_barrier(++ep);
    }
}

// ---------------------------------------------------------------------------
// tf32 split-3 MMA GEMM for xg of layers 1,2 (K = 1024). (unchanged, passing)
// ---------------------------------------------------------------------------
#define XKC   32
#define XLD   36
#define XA_F  (128 * XLD)
#define XB_F  (64 * XLD)
#define XST_F (XA_F + XB_F)

__global__ __launch_bounds__(128, 2) void gemm_xg_tf32_kernel(
    int a_sel, const float* __restrict__ W, const float* __restrict__ bias)
{
    const float* A = (a_sel == 1) ? g_yA : g_yB;
    const int K = HID;

    extern __shared__ float xs[];
    const int tid  = threadIdx.x;
    const int warp = tid >> 5;
    const int lane = tid & 31;
    const int g    = lane >> 2;
    const int tq   = lane & 3;

    const int n0 = blockIdx.x * 64;
    const int m0 = blockIdx.y * 128;
    const int wm = (warp & 1) * 64;
    const int wn = (warp >> 1) * 32;

    const uint32_t s_base = (uint32_t)__cvta_generic_to_shared(xs);

    float acc[4][4][4];
#pragma unroll
    for (int mi = 0; mi < 4; mi++)
#pragma unroll
        for (int ni = 0; ni < 4; ni++)
#pragma unroll
            for (int r = 0; r < 4; r++) acc[mi][ni][r] = 0.f;

    auto load_stage = [&](int ch, int buf) {
        const int k0 = ch * XKC;
        uint32_t dstA = s_base + (uint32_t)buf * XST_F * 4;
        uint32_t dstB = dstA + XA_F * 4;
#pragma unroll
        for (int j = 0; j < 8; j++) {
            int o = tid + j * 128;
            int row = o >> 3, seg = o & 7;
            cp_async16(dstA + (uint32_t)(row * XLD + seg * 4) * 4,
                       A + (size_t)(m0 + row) * K + k0 + seg * 4);
        }
#pragma unroll
        for (int j = 0; j < 4; j++) {
            int o = tid + j * 128;
            int row = o >> 3, seg = o & 7;
            cp_async16(dstB + (uint32_t)(row * XLD + seg * 4) * 4,
                       W + (size_t)(n0 + row) * K + k0 + seg * 4);
        }
    };

    const int NCH = K / XKC;
    load_stage(0, 0); cp_commit();
    load_stage(1, 1); cp_commit();

    for (int ch = 0; ch < NCH; ch++) {
        cp_wait<1>();
        __syncthreads();
        const float* As = xs + (ch & 1) * XST_F;
        const float* Bs = As + XA_F;

#pragma unroll
        for (int ks = 0; ks < 4; ks++) {
            const int k = ks * 8;
            uint32_t ahi[4][4], alo[4][4];
#pragma unroll
            for (int mi = 0; mi < 4; mi++) {
                int rbase = wm + mi * 16 + g;
                float r0 = As[(rbase)     * XLD + k + tq];
                float r1 = As[(rbase + 8) * XLD + k + tq];
                float r2 = As[(rbase)     * XLD + k + tq + 4];
                float r3 = As[(rbase + 8) * XLD + k + tq + 4];
                ahi[mi][0] = f2tf32(r0); alo[mi][0] = f2tf32(r0 - __uint_as_float(ahi[mi][0]));
                ahi[mi][1] = f2tf32(r1); alo[mi][1] = f2tf32(r1 - __uint_as_float(ahi[mi][1]));
                ahi[mi][2] = f2tf32(r2); alo[mi][2] = f2tf32(r2 - __uint_as_float(ahi[mi][2]));
                ahi[mi][3] = f2tf32(r3); alo[mi][3] = f2tf32(r3 - __uint_as_float(ahi[mi][3]));
            }
            uint32_t bhi[4][2], blo[4][2];
#pragma unroll
            for (int ni = 0; ni < 4; ni++) {
                int nbase = wn + ni * 8 + g;
                float r0 = Bs[nbase * XLD + k + tq];
                float r1 = Bs[nbase * XLD + k + tq + 4];
                bhi[ni][0] = f2tf32(r0); blo[ni][0] = f2tf32(r0 - __uint_as_float(bhi[ni][0]));
                bhi[ni][1] = f2tf32(r1); blo[ni][1] = f2tf32(r1 - __uint_as_float(bhi[ni][1]));
            }
#pragma unroll
            for (int mi = 0; mi < 4; mi++)
#pragma unroll
                for (int ni = 0; ni < 4; ni++) {
                    float* c = acc[mi][ni];
                    mma_tf32(c[0], c[1], c[2], c[3],
                             ahi[mi][0], ahi[mi][1], ahi[mi][2], ahi[mi][3],
                             bhi[ni][0], bhi[ni][1]);
                    mma_tf32(c[0], c[1], c[2], c[3],
                             ahi[mi][0], ahi[mi][1], ahi[mi][2], ahi[mi][3],
                             blo[ni][0], blo[ni][1]);
                    mma_tf32(c[0], c[1], c[2], c[3],
                             alo[mi][0], alo[mi][1], alo[mi][2], alo[mi][3],
                             bhi[ni][0], bhi[ni][1]);
                }
        }

        __syncthreads();
        if (ch + 2 < NCH) load_stage(ch + 2, ch & 1);
        cp_commit();
    }

#pragma unroll
    for (int mi = 0; mi < 4; mi++) {
        int r0 = m0 + wm + mi * 16 + g;
#pragma unroll
        for (int ni = 0; ni < 4; ni++) {
            int cb = n0 + wn + ni * 8 + 2 * tq;
            float2 bia = *(const float2*)&bias[cb];
            float* c = acc[mi][ni];
            *(float2*)&g_xg[(size_t)r0 * G3 + cb] =
                make_float2(c[0] + bia.x, c[1] + bia.y);
            *(float2*)&g_xg[(size_t)(r0 + 8) * G3 + cb] =
                make_float2(c[2] + bia.x, c[3] + bia.y);
        }
    }
}

// ---------------------------------------------------------------------------
// fp32 SGEMM for layer-0 xg (K = 118). (unchanged, passing)
// ---------------------------------------------------------------------------
__global__ __launch_bounds__(256) void gemm_xg_kernel(
    const float* __restrict__ x_in, int K,
    const float* __restrict__ W, const float* __restrict__ bias)
{
    const float* A = x_in;

    __shared__ float As[8][128];
    __shared__ float Bs[8][128];

    const int n0 = blockIdx.x * 128;
    const int m0 = blockIdx.y * 128;
    const int tid = threadIdx.x;
    const int tx = tid & 15;
    const int ty = tid >> 4;

    float acc[8][8];
#pragma unroll
    for (int i = 0; i < 8; i++)
#pragma unroll
        for (int j = 0; j < 8; j++) acc[i][j] = 0.f;

    const int nkt = (K + 7) >> 3;
    for (int kt = 0; kt < nkt; kt++) {
        const int k0 = kt << 3;
#pragma unroll
        for (int i = 0; i < 4; i++) {
            int ii = tid + i * 256;
            int m = ii >> 3, k = ii & 7;
            As[k][m] = (k0 + k < K) ? A[(size_t)(m0 + m) * K + (k0 + k)] : 0.f;
        }
#pragma unroll
        for (int i = 0; i < 4; i++) {
            int ii = tid + i * 256;
            int n = ii >> 3, k = ii & 7;
            Bs[k][n] = (k0 + k < K) ? W[(size_t)(n0 + n) * K + (k0 + k)] : 0.f;
        }
        __syncthreads();
#pragma unroll
        for (int k = 0; k < 8; k++) {
            float a[8], b[8];
#pragma unroll
            for (int i = 0; i < 8; i++) a[i] = As[k][ty * 8 + i];
#pragma unroll
            for (int j = 0; j < 8; j++) b[j] = Bs[k][tx * 8 + j];
#pragma unroll
            for (int i = 0; i < 8; i++)
#pragma unroll
                for (int j = 0; j < 8; j++)
                    acc[i][j] = fmaf(a[i], b[j], acc[i][j]);
        }
        __syncthreads();
    }

#pragma unroll
    for (int i = 0; i < 8; i++) {
        size_t row = (size_t)(m0 + ty * 8 + i) * G3;
#pragma unroll
        for (int j = 0; j < 8; j++) {
            int n = n0 + tx * 8 + j;
            g_xg[row + n] = acc[i][j] + bias[n];
        }
    }
}

// ---------------------------------------------------------------------------
// Final linear: out[b] = dot(h_last[b,:], W_lin) + b_lin
// ---------------------------------------------------------------------------
__global__ __launch_bounds__(256) void final_kernel(
    const float* __restrict__ Wlin, const float* __restrict__ blin,
    float* __restrict__ out)
{
    const int b = blockIdx.x;
    const float* h = g_hb + b * HID;
    float s = 0.f;
    for (int k = threadIdx.x; k < HID; k += 256) s += h[k] * Wlin[k];
#pragma unroll
    for (int o = 16; o > 0; o >>= 1) s += __shfl_down_sync(0xffffffffu, s, o);
    __shared__ float red[8];
    if ((threadIdx.x & 31) == 0) red[threadIdx.x >> 5] = s;
    __syncthreads();
    if (threadIdx.x < 8) {
        s = red[threadIdx.x];
#pragma unroll
        for (int o = 4; o > 0; o >>= 1) s += __shfl_down_sync(0xffu, s, o);
        if (threadIdx.x == 0) out[b] = s + blin[0];
    }
}

// ---------------------------------------------------------------------------
extern "C" void kernel_launch(void* const* d_in, const int* in_sizes, int n_in,
                              void* d_out, int out_size)
{
    const float* x      = (const float*)d_in[0];
    const float* W_ih0  = (const float*)d_in[1];
    const float* W_ih12 = (const float*)d_in[2];
    const float* W_hh   = (const float*)d_in[3];
    const float* b_ih   = (const float*)d_in[4];
    const float* b_hh   = (const float*)d_in[5];
    const float* W_lin  = (const float*)d_in[6];
    const float* b_lin  = (const float*)d_in[7];
    float* out = (float*)d_out;

    cudaFuncSetAttribute(gru_layer_kernel,
                         cudaFuncAttributeMaxDynamicSharedMemorySize, GSM_BYTES);
    const int smem_xg = 2 * XST_F * sizeof(float);
    cudaFuncSetAttribute(gemm_xg_tf32_kernel,
                         cudaFuncAttributeMaxDynamicSharedMemorySize, smem_xg);

    for (int l = 0; l < 3; l++) {
        const int    ysel  = (l == 0) ? 1 : (l == 1 ? 2 : 0);
        const float* Whh_l = W_hh + (size_t)l * G3 * HID;
        const float* bih_l = b_ih + (size_t)l * G3;
        const float* bhh_l = b_hh + (size_t)l * G3;

        if (l == 0) {
            dim3 ggrid(G3 / 128, BT / 128);
            gemm_xg_kernel<<<ggrid, 256>>>(x, DIN0, W_ih0, bih_l);
        } else {
            const float* Wih = W_ih12 + (size_t)(l - 1) * G3 * HID;
            dim3 ggrid(G3 / 64, BT / 128);
            gemm_xg_tf32_kernel<<<ggrid, 128, smem_xg>>>(l, Wih, bih_l);
        }

        gru_layer_kernel<<<NBLK, GNT, GSM_BYTES>>>(Whh_l, bhh_l, ysel);
    }

    final_kernel<<<BATCH, 256>>>(W_lin, b_lin, out);
}